// round 4
// baseline (speedup 1.0000x reference)
#include <cuda_runtime.h>
#include <cuda_bf16.h>
#include <math.h>

// HashedInterpolator: 3-D hash-grid trilinear interpolation.
// position: [B,3] f32 in [0,1);  hash_table: [524288,4] f32;  out: [B,4] f32.
//
// R4: lane-pair x-merge (R3) + 2 points per thread for MLP=8 gathers/lane.
// hash dim-x prime is 1, so for even lx the two x-corners are consecutive
// table rows -> same 128B line -> one L1 wavefront for the lane pair.

#define HG_ENTRIES 524288
#define HG_MASK    (HG_ENTRIES - 1)
#define HG_P1      19349663u
#define HG_P2      83492791u

#define TPB   256
#define HALF  (TPB / 2)        // 128 lane-pairs -> 128 point-slots per half
#define PPB   (TPB)            // 256 points per block (2 per lane pair)

__global__ __launch_bounds__(TPB) void hashed_interp_kernel(
    const float* __restrict__ pos,
    const float4* __restrict__ table,
    float4* __restrict__ out,
    int batch)
{
    __shared__ float sp[3 * PPB];

    int t = threadIdx.x;
    int base = blockIdx.x * PPB;          // first point of this block

    // Stage this block's positions (3*PPB floats = 192 float4s) coalesced.
    {
        int nfloats = 3 * (batch - base);
        if (nfloats > 3 * PPB) nfloats = 3 * PPB;
        const float4* src = (const float4*)(pos + 3 * base);  // 3072B-aligned
        int nvec = nfloats >> 2;
        if (t < nvec) ((float4*)sp)[t] = src[t];
        int rem = nfloats & 3;
        if (t < rem) sp[(nvec << 2) + t] = pos[3 * base + (nvec << 2) + t];
    }
    __syncthreads();

    int slot = t >> 1;          // 0..127
    int xbit = t & 1;           // which x-corner this lane owns
    int iA   = base + slot;
    int iB   = base + slot + HALF;
    bool hasA = iA < batch;
    bool hasB = iB < batch;

    const float inv = 1.0f / 512.0f;   // exact

    // ---- point A setup ----
    float axw = 0.f, ay0 = 0.f, ay1 = 0.f, az0 = 0.f, az1 = 0.f;
    unsigned a00 = 0, a01 = 0, a10 = 0, a11 = 0;
    if (hasA) {
        float px = sp[3 * slot + 0];
        float py = sp[3 * slot + 1];
        float pz = sp[3 * slot + 2];
        int lx = (int)floorf(px * 512.0f);
        int ly = (int)floorf(py * 512.0f);
        int lz = (int)floorf(pz * 512.0f);
        float wx0 = (px - (float)lx * inv) * 512.0f;
        float wx1 = ((float)(lx + 1) * inv - px) * 512.0f;
        ay0 = (py - (float)ly * inv) * 512.0f;
        ay1 = ((float)(ly + 1) * inv - py) * 512.0f;
        az0 = (pz - (float)lz * inv) * 512.0f;
        az1 = ((float)(lz + 1) * inv - pz) * 512.0f;
        axw = xbit ? wx1 : wx0;
        unsigned hx  = (unsigned)(lx + xbit);
        unsigned hy0 = (unsigned)ly * HG_P1;
        unsigned hy1 = (unsigned)(ly + 1) * HG_P1;
        unsigned hz0 = (unsigned)lz * HG_P2;
        unsigned hz1 = (unsigned)(lz + 1) * HG_P2;
        a00 = (hx ^ hy0 ^ hz0) & HG_MASK;
        a01 = (hx ^ hy0 ^ hz1) & HG_MASK;
        a10 = (hx ^ hy1 ^ hz0) & HG_MASK;
        a11 = (hx ^ hy1 ^ hz1) & HG_MASK;
    }

    // ---- point B setup ----
    float bxw = 0.f, by0 = 0.f, by1 = 0.f, bz0 = 0.f, bz1 = 0.f;
    unsigned b00 = 0, b01 = 0, b10 = 0, b11 = 0;
    if (hasB) {
        int s2 = slot + HALF;
        float px = sp[3 * s2 + 0];
        float py = sp[3 * s2 + 1];
        float pz = sp[3 * s2 + 2];
        int lx = (int)floorf(px * 512.0f);
        int ly = (int)floorf(py * 512.0f);
        int lz = (int)floorf(pz * 512.0f);
        float wx0 = (px - (float)lx * inv) * 512.0f;
        float wx1 = ((float)(lx + 1) * inv - px) * 512.0f;
        by0 = (py - (float)ly * inv) * 512.0f;
        by1 = ((float)(ly + 1) * inv - py) * 512.0f;
        bz0 = (pz - (float)lz * inv) * 512.0f;
        bz1 = ((float)(lz + 1) * inv - pz) * 512.0f;
        bxw = xbit ? wx1 : wx0;
        unsigned hx  = (unsigned)(lx + xbit);
        unsigned hy0 = (unsigned)ly * HG_P1;
        unsigned hy1 = (unsigned)(ly + 1) * HG_P1;
        unsigned hz0 = (unsigned)lz * HG_P2;
        unsigned hz1 = (unsigned)(lz + 1) * HG_P2;
        b00 = (hx ^ hy0 ^ hz0) & HG_MASK;
        b01 = (hx ^ hy0 ^ hz1) & HG_MASK;
        b10 = (hx ^ hy1 ^ hz0) & HG_MASK;
        b11 = (hx ^ hy1 ^ hz1) & HG_MASK;
    }

    // ---- issue all 8 gathers (MLP=8 per lane) ----
    float4 vA00, vA01, vA10, vA11, vB00, vB01, vB10, vB11;
    if (hasA) {
        vA00 = __ldcg(&table[a00]);
        vA01 = __ldcg(&table[a01]);
        vA10 = __ldcg(&table[a10]);
        vA11 = __ldcg(&table[a11]);
    }
    if (hasB) {
        vB00 = __ldcg(&table[b00]);
        vB01 = __ldcg(&table[b01]);
        vB10 = __ldcg(&table[b10]);
        vB11 = __ldcg(&table[b11]);
    }

    // ---- accumulate A ----
    if (hasA) {
        float w00 = axw * ay0 * az0;
        float w01 = axw * ay0 * az1;
        float w10 = axw * ay1 * az0;
        float w11 = axw * ay1 * az1;
        float4 acc;
        acc.x = vA00.x * w00;  acc.y = vA00.y * w00;
        acc.z = vA00.z * w00;  acc.w = vA00.w * w00;
        acc.x = fmaf(vA01.x, w01, acc.x);  acc.y = fmaf(vA01.y, w01, acc.y);
        acc.z = fmaf(vA01.z, w01, acc.z);  acc.w = fmaf(vA01.w, w01, acc.w);
        acc.x = fmaf(vA10.x, w10, acc.x);  acc.y = fmaf(vA10.y, w10, acc.y);
        acc.z = fmaf(vA10.z, w10, acc.z);  acc.w = fmaf(vA10.w, w10, acc.w);
        acc.x = fmaf(vA11.x, w11, acc.x);  acc.y = fmaf(vA11.y, w11, acc.y);
        acc.z = fmaf(vA11.z, w11, acc.z);  acc.w = fmaf(vA11.w, w11, acc.w);

        acc.x += __shfl_xor_sync(0xffffffffu, acc.x, 1);
        acc.y += __shfl_xor_sync(0xffffffffu, acc.y, 1);
        acc.z += __shfl_xor_sync(0xffffffffu, acc.z, 1);
        acc.w += __shfl_xor_sync(0xffffffffu, acc.w, 1);
        if (xbit == 0) __stcs(&out[iA], acc);
    }

    // ---- accumulate B ----
    if (hasB) {
        float w00 = bxw * by0 * bz0;
        float w01 = bxw * by0 * bz1;
        float w10 = bxw * by1 * bz0;
        float w11 = bxw * by1 * bz1;
        float4 acc;
        acc.x = vB00.x * w00;  acc.y = vB00.y * w00;
        acc.z = vB00.z * w00;  acc.w = vB00.w * w00;
        acc.x = fmaf(vB01.x, w01, acc.x);  acc.y = fmaf(vB01.y, w01, acc.y);
        acc.z = fmaf(vB01.z, w01, acc.z);  acc.w = fmaf(vB01.w, w01, acc.w);
        acc.x = fmaf(vB10.x, w10, acc.x);  acc.y = fmaf(vB10.y, w10, acc.y);
        acc.z = fmaf(vB10.z, w10, acc.z);  acc.w = fmaf(vB10.w, w10, acc.w);
        acc.x = fmaf(vB11.x, w11, acc.x);  acc.y = fmaf(vB11.y, w11, acc.y);
        acc.z = fmaf(vB11.z, w11, acc.z);  acc.w = fmaf(vB11.w, w11, acc.w);

        acc.x += __shfl_xor_sync(0xffffffffu, acc.x, 1);
        acc.y += __shfl_xor_sync(0xffffffffu, acc.y, 1);
        acc.z += __shfl_xor_sync(0xffffffffu, acc.z, 1);
        acc.w += __shfl_xor_sync(0xffffffffu, acc.w, 1);
        if (xbit == 0) __stcs(&out[iB], acc);
    }
}

extern "C" void kernel_launch(void* const* d_in, const int* in_sizes, int n_in,
                              void* d_out, int out_size)
{
    const float* pos = (const float*)d_in[0];
    const float4* table = (const float4*)d_in[1];
    float4* out = (float4*)d_out;
    int batch = in_sizes[0] / 3;

    int blocks = (batch + PPB - 1) / PPB;
    hashed_interp_kernel<<<blocks, TPB>>>(pos, table, out, batch);
}